// round 16
// baseline (speedup 1.0000x reference)
#include <cuda_runtime.h>
#include <cuda_fp16.h>
#include <math_constants.h>

// Fused GAT forward, single-launch role-split edition.
// N=50000, deg=16 (CSR), H=4, D=32.
//
// One kernel, two block roles:
//   blocks [0, NC):  grid-stride fp32->fp16 convert of in_feat into g_feat16
//                    (uint4 stores). NC=296 = 2 blocks/SM -> wave 1 holds
//                    converters AND GAT blocks side by side.
//   blocks [NC, ..): R14's pair-GAT verbatim. Score phase (indptr, col_idx,
//                    attn gathers, xor-shuffle softmax, smem alpha park)
//                    overlaps the convert; a counter gate (thread0 poll +
//                    __syncthreads) releases the fp16 gather only after all
//                    NC converter blocks signalled. Tail GAT block resets the
//                    counters so CUDA-graph replays stay deterministic.
// Aggregation: lane owns fp16 words {col*64+l} and {col*64+32+l}; every
// gather LDG.32 covers exactly one 128B line. fp32 accumulate.

#define NEG_SLOPE 0.2f
#define WPB 8
#define MAX_N 50000
#define NC_BLOCKS 296

__device__ __align__(16) unsigned int g_feat16[(size_t)MAX_N * 64];
__device__ int g_conv_done = 0;   // converter blocks finished
__device__ int g_fin       = 0;   // GAT blocks finished (for reset)

__global__ void __launch_bounds__(WPB * 32, 4)
fused_gat_onekernel(const float*  __restrict__ attn_row,   // [N,4]
                    const float*  __restrict__ attn_col,   // [N,4]
                    const int*    __restrict__ row_indptr, // [N+1]
                    const int*    __restrict__ col_idx,    // [E]
                    const float4* __restrict__ feat_src,   // in_feat as float4
                    float*        __restrict__ out,        // [N,4,32]
                    int n, int n8, int gat_blocks)
{
    const unsigned FULL = 0xffffffffu;

    // ======================= converter role =======================
    if ((int)blockIdx.x < NC_BLOCKS) {
        for (int i = blockIdx.x * 256 + threadIdx.x; i < n8;
             i += NC_BLOCKS * 256) {
            const float4 a = feat_src[2 * i];
            const float4 b = feat_src[2 * i + 1];
            const __half2 h0 = __floats2half2_rn(a.x, a.y);
            const __half2 h1 = __floats2half2_rn(a.z, a.w);
            const __half2 h2 = __floats2half2_rn(b.x, b.y);
            const __half2 h3 = __floats2half2_rn(b.z, b.w);
            uint4 u;
            u.x = *reinterpret_cast<const unsigned int*>(&h0);
            u.y = *reinterpret_cast<const unsigned int*>(&h1);
            u.z = *reinterpret_cast<const unsigned int*>(&h2);
            u.w = *reinterpret_cast<const unsigned int*>(&h3);
            ((uint4*)g_feat16)[i] = u;
        }
        __syncthreads();
        if (threadIdx.x == 0) {
            __threadfence();
            atomicAdd(&g_conv_done, 1);
        }
        return;
    }

    // ========================= GAT role =========================
    __shared__ __align__(16) int    s_col[WPB][32];
    // [warp][p][node-half][edge(16 padded to 18)] : {alpha_p, alpha_{p+2}}
    __shared__ __align__(16) float2 s_ap[WPB][2][2][18];

    const int lane  = threadIdx.x & 31;
    const int w     = threadIdx.x >> 5;
    const int pair  = ((int)blockIdx.x - NC_BLOCKS) * WPB + w;
    const int node0 = pair * 2;

    const int  half = lane >> 4;        // which node of the pair my lane scores
    const int  el   = lane & 15;        // edge slot within that node
    int        node = node0 + half;
    const bool pvalid = (node0 < n);
    const bool nvalid = pvalid && (node < n);
    if (!nvalid) node = n - 1;          // clamp for safe loads

    int col = 0;
    float a0 = 0.f, a1 = 0.f, a2 = 0.f, a3 = 0.f;

    if (pvalid) {
        const int start = __ldg(&row_indptr[node]);
        const int deg   = __ldg(&row_indptr[node + 1]) - start;

        // ---- per-edge scores, all 4 heads (independent of g_feat16) ----
        const float4 ar = __ldg((const float4*)attn_row + node);

        float s0 = -CUDART_INF_F, s1 = -CUDART_INF_F,
              s2 = -CUDART_INF_F, s3 = -CUDART_INF_F;

        const bool edge_lane = nvalid && (el < deg);
        if (edge_lane) {
            col = __ldg(&col_idx[start + el]);
            const float4 ac = __ldg((const float4*)attn_col + col);
            float t0 = ar.x + ac.x, t1 = ar.y + ac.y;
            float t2 = ar.z + ac.z, t3 = ar.w + ac.w;
            s0 = (t0 > 0.0f) ? t0 : NEG_SLOPE * t0;
            s1 = (t1 > 0.0f) ? t1 : NEG_SLOPE * t1;
            s2 = (t2 > 0.0f) ? t2 : NEG_SLOPE * t2;
            s3 = (t3 > 0.0f) ? t3 : NEG_SLOPE * t3;
        }

        // ---- shuffle softmax per 16-lane half (xor 8,4,2,1) ----
        float m0 = s0, m1 = s1, m2 = s2, m3 = s3;
        #pragma unroll
        for (int k = 8; k > 0; k >>= 1) {
            m0 = fmaxf(m0, __shfl_xor_sync(FULL, m0, k));
            m1 = fmaxf(m1, __shfl_xor_sync(FULL, m1, k));
            m2 = fmaxf(m2, __shfl_xor_sync(FULL, m2, k));
            m3 = fmaxf(m3, __shfl_xor_sync(FULL, m3, k));
        }

        float e0 = 0.f, e1 = 0.f, e2 = 0.f, e3 = 0.f;
        if (edge_lane) {
            e0 = __expf(s0 - m0);
            e1 = __expf(s1 - m1);
            e2 = __expf(s2 - m2);
            e3 = __expf(s3 - m3);
        }

        float d0 = e0, d1 = e1, d2 = e2, d3 = e3;
        #pragma unroll
        for (int k = 8; k > 0; k >>= 1) {
            d0 += __shfl_xor_sync(FULL, d0, k);
            d1 += __shfl_xor_sync(FULL, d1, k);
            d2 += __shfl_xor_sync(FULL, d2, k);
            d3 += __shfl_xor_sync(FULL, d3, k);
        }

        a0 = edge_lane ? __fdividef(e0, d0) : 0.f;
        a1 = edge_lane ? __fdividef(e1, d1) : 0.f;
        a2 = edge_lane ? __fdividef(e2, d2) : 0.f;
        a3 = edge_lane ? __fdividef(e3, d3) : 0.f;

        s_col[w][lane]       = col;
        s_ap[w][0][half][el] = make_float2(a0, a2);   // heads (0,2)
        s_ap[w][1][half][el] = make_float2(a1, a3);   // heads (1,3)
    }

    // ---- gate: wait for all converter blocks (block-level, low traffic) ----
    if (threadIdx.x == 0) {
        while (*((volatile int*)&g_conv_done) != NC_BLOCKS)
            __nanosleep(512);
        __threadfence();
    }
    __syncthreads();   // releases all warps; also orders smem alpha park

    if (pvalid) {
        // ---- aggregation: lane owns fp16 words {l} and {32+l} per row ----
        const int p = half;   // low-word head p, high-word head p+2
        const unsigned int* __restrict__ fb = g_feat16;

        #pragma unroll
        for (int n2 = 0; n2 < 2; ++n2) {
            const int nodeX = node0 + n2;
            if (nodeX >= n) break;

            const int4*   __restrict__ cp = (const int4*)&s_col[w][n2 * 16];
            const float4* __restrict__ ap = (const float4*)&s_ap[w][p][n2][0];

            float2 accL = make_float2(0.f, 0.f);
            float2 accH = make_float2(0.f, 0.f);

            #pragma unroll
            for (int j4 = 0; j4 < 4; ++j4) {
                const int4   c  = cp[j4];          // 4 neighbor ids
                const float4 A0 = ap[j4 * 2];      // edges 0,1: {aL,aH,aL,aH}
                const float4 A1 = ap[j4 * 2 + 1];  // edges 2,3

                unsigned b, u0, u1;
                float2 f0, f1;

                b  = (unsigned)c.x * 64u;
                u0 = __ldg(fb + b + lane);
                u1 = __ldg(fb + b + 32 + lane);
                f0 = __half22float2(*reinterpret_cast<const __half2*>(&u0));
                f1 = __half22float2(*reinterpret_cast<const __half2*>(&u1));
                accL.x = fmaf(A0.x, f0.x, accL.x); accL.y = fmaf(A0.x, f0.y, accL.y);
                accH.x = fmaf(A0.y, f1.x, accH.x); accH.y = fmaf(A0.y, f1.y, accH.y);

                b  = (unsigned)c.y * 64u;
                u0 = __ldg(fb + b + lane);
                u1 = __ldg(fb + b + 32 + lane);
                f0 = __half22float2(*reinterpret_cast<const __half2*>(&u0));
                f1 = __half22float2(*reinterpret_cast<const __half2*>(&u1));
                accL.x = fmaf(A0.z, f0.x, accL.x); accL.y = fmaf(A0.z, f0.y, accL.y);
                accH.x = fmaf(A0.w, f1.x, accH.x); accH.y = fmaf(A0.w, f1.y, accH.y);

                b  = (unsigned)c.z * 64u;
                u0 = __ldg(fb + b + lane);
                u1 = __ldg(fb + b + 32 + lane);
                f0 = __half22float2(*reinterpret_cast<const __half2*>(&u0));
                f1 = __half22float2(*reinterpret_cast<const __half2*>(&u1));
                accL.x = fmaf(A1.x, f0.x, accL.x); accL.y = fmaf(A1.x, f0.y, accL.y);
                accH.x = fmaf(A1.y, f1.x, accH.x); accH.y = fmaf(A1.y, f1.y, accH.y);

                b  = (unsigned)c.w * 64u;
                u0 = __ldg(fb + b + lane);
                u1 = __ldg(fb + b + 32 + lane);
                f0 = __half22float2(*reinterpret_cast<const __half2*>(&u0));
                f1 = __half22float2(*reinterpret_cast<const __half2*>(&u1));
                accL.x = fmaf(A1.z, f0.x, accL.x); accL.y = fmaf(A1.z, f0.y, accL.y);
                accH.x = fmaf(A1.w, f1.x, accH.x); accH.y = fmaf(A1.w, f1.y, accH.y);
            }

            // out[nodeX]: float2 at dims {2l,2l+1} and {64+2l,65+2l}
            float2* op = (float2*)out + (size_t)nodeX * 64;
            op[lane]      = accL;
            op[32 + lane] = accH;
        }
    }

    // ---- tail reset for graph-replay determinism ----
    __syncthreads();
    if (threadIdx.x == 0) {
        const int f = atomicAdd(&g_fin, 1);
        if (f == gat_blocks - 1) {
            g_conv_done = 0;
            g_fin       = 0;
            __threadfence();
        }
    }
}

extern "C" void kernel_launch(void* const* d_in, const int* in_sizes, int n_in,
                              void* d_out, int out_size)
{
    const float* attn_row   = (const float*)d_in[0];
    const float* attn_col   = (const float*)d_in[1];
    const float* in_feat    = (const float*)d_in[2];
    const int*   row_indptr = (const int*)  d_in[3];
    const int*   col_idx    = (const int*)  d_in[4];
    float*       out        = (float*)      d_out;

    const int n  = in_sizes[3] - 1;   // N from indptr length
    const int n8 = in_sizes[2] / 8;   // uint4 count of fp16 copy

    const int pairs      = (n + 1) / 2;
    const int gat_blocks = (pairs + WPB - 1) / WPB;
    const int blocks     = NC_BLOCKS + gat_blocks;

    fused_gat_onekernel<<<blocks, WPB * 32>>>(attn_row, attn_col,
                                              row_indptr, col_idx,
                                              (const float4*)in_feat,
                                              out, n, n8, gat_blocks);
}

// round 17
// speedup vs baseline: 1.1301x; 1.1301x over previous
#include <cuda_runtime.h>
#include <cuda_fp16.h>
#include <math_constants.h>

// Fused GAT forward. N=50000, deg=16 (CSR), H=4, D=32.
//
// K1 (convert, PDL primary): in_feat fp32 -> g_feat16 fp16 (uint4 stores).
// K2 (gat, PDL secondary): warp per NODE PAIR, deep-MLP edition.
//   __launch_bounds__(256,3): 84-reg budget lets ptxas batch BOTH nodes'
//   64 gather LDG.32s (each covering exactly one 128B line) before the
//   consume phase -> ~2x per-warp MLP, one exposed L2 round-trip per pair.
//   The node loop is branchless (clamped loads, predicated stores) so the
//   scheduler can cross-node reorder. Evidence: 48regs/54%occ=27.7us,
//   62regs/44%occ=26.7us -> MLP beats occupancy for this kernel.

#define NEG_SLOPE 0.2f
#define WPB 8
#define MAX_N 50000

__device__ __align__(16) unsigned int g_feat16[(size_t)MAX_N * 64];

// ---------------- K1: fp32 -> fp16 convert (PDL primary) ----------------
__global__ void __launch_bounds__(256)
gat_convert_kernel(const float4* __restrict__ src, int n8)
{
    asm volatile("griddepcontrol.launch_dependents;" ::: "memory");

    int i = blockIdx.x * blockDim.x + threadIdx.x;
    if (i >= n8) return;
    const float4 a = src[2 * i];
    const float4 b = src[2 * i + 1];
    const __half2 h0 = __floats2half2_rn(a.x, a.y);
    const __half2 h1 = __floats2half2_rn(a.z, a.w);
    const __half2 h2 = __floats2half2_rn(b.x, b.y);
    const __half2 h3 = __floats2half2_rn(b.z, b.w);
    uint4 u;
    u.x = *reinterpret_cast<const unsigned int*>(&h0);
    u.y = *reinterpret_cast<const unsigned int*>(&h1);
    u.z = *reinterpret_cast<const unsigned int*>(&h2);
    u.w = *reinterpret_cast<const unsigned int*>(&h3);
    ((uint4*)g_feat16)[i] = u;
}

// ---------------- K2: fused GAT pair kernel (PDL secondary) ----------------
__global__ void __launch_bounds__(WPB * 32, 3)
fused_gat_pair_kernel(const float* __restrict__ attn_row,   // [N,4]
                      const float* __restrict__ attn_col,   // [N,4]
                      const int*   __restrict__ row_indptr, // [N+1]
                      const int*   __restrict__ col_idx,    // [E]
                      float*       __restrict__ out,        // [N,4,32]
                      int n)
{
    const unsigned FULL = 0xffffffffu;
    __shared__ __align__(16) int    s_col[WPB][32];
    // [warp][p][node-half][edge(16 padded to 18)] : {alpha_p, alpha_{p+2}}
    __shared__ __align__(16) float2 s_ap[WPB][2][2][18];

    const int lane  = threadIdx.x & 31;
    const int w     = threadIdx.x >> 5;
    const int pair  = blockIdx.x * WPB + w;
    const int node0 = pair * 2;
    if (node0 >= n) return;

    const int  half = lane >> 4;        // which node of the pair my lane scores
    const int  el   = lane & 15;        // edge slot within that node
    int        node = node0 + half;
    const bool nvalid = (node < n);
    if (!nvalid) node = n - 1;          // clamp for safe loads

    const int start = __ldg(&row_indptr[node]);
    const int deg   = __ldg(&row_indptr[node + 1]) - start;

    // ---- per-edge scores, all 4 heads (independent of g_feat16) ----
    const float4 ar = __ldg((const float4*)attn_row + node);

    int col = 0;
    float s0 = -CUDART_INF_F, s1 = -CUDART_INF_F,
          s2 = -CUDART_INF_F, s3 = -CUDART_INF_F;

    const bool edge_lane = nvalid && (el < deg);
    if (edge_lane) {
        col = __ldg(&col_idx[start + el]);
        const float4 ac = __ldg((const float4*)attn_col + col);
        float t0 = ar.x + ac.x, t1 = ar.y + ac.y;
        float t2 = ar.z + ac.z, t3 = ar.w + ac.w;
        s0 = (t0 > 0.0f) ? t0 : NEG_SLOPE * t0;
        s1 = (t1 > 0.0f) ? t1 : NEG_SLOPE * t1;
        s2 = (t2 > 0.0f) ? t2 : NEG_SLOPE * t2;
        s3 = (t3 > 0.0f) ? t3 : NEG_SLOPE * t3;
    }

    // ---- shuffle softmax per 16-lane half (xor 8,4,2,1 stays in half) ----
    float m0 = s0, m1 = s1, m2 = s2, m3 = s3;
    #pragma unroll
    for (int k = 8; k > 0; k >>= 1) {
        m0 = fmaxf(m0, __shfl_xor_sync(FULL, m0, k));
        m1 = fmaxf(m1, __shfl_xor_sync(FULL, m1, k));
        m2 = fmaxf(m2, __shfl_xor_sync(FULL, m2, k));
        m3 = fmaxf(m3, __shfl_xor_sync(FULL, m3, k));
    }

    float e0 = 0.f, e1 = 0.f, e2 = 0.f, e3 = 0.f;
    if (edge_lane) {
        e0 = __expf(s0 - m0);
        e1 = __expf(s1 - m1);
        e2 = __expf(s2 - m2);
        e3 = __expf(s3 - m3);
    }

    float d0 = e0, d1 = e1, d2 = e2, d3 = e3;
    #pragma unroll
    for (int k = 8; k > 0; k >>= 1) {
        d0 += __shfl_xor_sync(FULL, d0, k);
        d1 += __shfl_xor_sync(FULL, d1, k);
        d2 += __shfl_xor_sync(FULL, d2, k);
        d3 += __shfl_xor_sync(FULL, d3, k);
    }

    const float a0 = edge_lane ? __fdividef(e0, d0) : 0.f;
    const float a1 = edge_lane ? __fdividef(e1, d1) : 0.f;
    const float a2 = edge_lane ? __fdividef(e2, d2) : 0.f;
    const float a3 = edge_lane ? __fdividef(e3, d3) : 0.f;

    s_col[w][lane]       = col;
    s_ap[w][0][half][el] = make_float2(a0, a2);   // heads (0,2)
    s_ap[w][1][half][el] = make_float2(a1, a3);   // heads (1,3)
    __syncwarp(FULL);

    // ---- wait for convert kernel's g_feat16 before gathering ----
    asm volatile("griddepcontrol.wait;" ::: "memory");

    // ---- aggregation: branchless over both nodes so ptxas can batch
    //      all 64 gather LDGs. Invalid tail node gathers col0*alpha0 = 0
    //      from clamped smem data; only the store is predicated. ----
    const int p = half;   // low-word head p, high-word head p+2
    const unsigned int* __restrict__ fb = g_feat16;
    const bool store1 = (node0 + 1) < n;

    #pragma unroll
    for (int n2 = 0; n2 < 2; ++n2) {
        const int4*   __restrict__ cp = (const int4*)&s_col[w][n2 * 16];
        const float4* __restrict__ ap = (const float4*)&s_ap[w][p][n2][0];

        float2 accL = make_float2(0.f, 0.f);
        float2 accH = make_float2(0.f, 0.f);

        #pragma unroll
        for (int j4 = 0; j4 < 4; ++j4) {
            const int4   c  = cp[j4];          // 4 neighbor ids (broadcast)
            const float4 A0 = ap[j4 * 2];      // edges 0,1: {aL,aH,aL,aH}
            const float4 A1 = ap[j4 * 2 + 1];  // edges 2,3

            unsigned b, u0, u1;
            float2 f0, f1;

            b  = (unsigned)c.x * 64u;
            u0 = __ldg(fb + b + lane);
            u1 = __ldg(fb + b + 32 + lane);
            f0 = __half22float2(*reinterpret_cast<const __half2*>(&u0));
            f1 = __half22float2(*reinterpret_cast<const __half2*>(&u1));
            accL.x = fmaf(A0.x, f0.x, accL.x); accL.y = fmaf(A0.x, f0.y, accL.y);
            accH.x = fmaf(A0.y, f1.x, accH.x); accH.y = fmaf(A0.y, f1.y, accH.y);

            b  = (unsigned)c.y * 64u;
            u0 = __ldg(fb + b + lane);
            u1 = __ldg(fb + b + 32 + lane);
            f0 = __half22float2(*reinterpret_cast<const __half2*>(&u0));
            f1 = __half22float2(*reinterpret_cast<const __half2*>(&u1));
            accL.x = fmaf(A0.z, f0.x, accL.x); accL.y = fmaf(A0.z, f0.y, accL.y);
            accH.x = fmaf(A0.w, f1.x, accH.x); accH.y = fmaf(A0.w, f1.y, accH.y);

            b  = (unsigned)c.z * 64u;
            u0 = __ldg(fb + b + lane);
            u1 = __ldg(fb + b + 32 + lane);
            f0 = __half22float2(*reinterpret_cast<const __half2*>(&u0));
            f1 = __half22float2(*reinterpret_cast<const __half2*>(&u1));
            accL.x = fmaf(A1.x, f0.x, accL.x); accL.y = fmaf(A1.x, f0.y, accL.y);
            accH.x = fmaf(A1.y, f1.x, accH.x); accH.y = fmaf(A1.y, f1.y, accH.y);

            b  = (unsigned)c.w * 64u;
            u0 = __ldg(fb + b + lane);
            u1 = __ldg(fb + b + 32 + lane);
            f0 = __half22float2(*reinterpret_cast<const __half2*>(&u0));
            f1 = __half22float2(*reinterpret_cast<const __half2*>(&u1));
            accL.x = fmaf(A1.z, f0.x, accL.x); accL.y = fmaf(A1.z, f0.y, accL.y);
            accH.x = fmaf(A1.w, f1.x, accH.x); accH.y = fmaf(A1.w, f1.y, accH.y);
        }

        // predicated store only (keeps the loop body branch-free)
        if (n2 == 0 || store1) {
            float2* op = (float2*)out + (size_t)(node0 + n2) * 64;
            op[lane]      = accL;
            op[32 + lane] = accH;
        }
    }
}

extern "C" void kernel_launch(void* const* d_in, const int* in_sizes, int n_in,
                              void* d_out, int out_size)
{
    const float* attn_row   = (const float*)d_in[0];
    const float* attn_col   = (const float*)d_in[1];
    const float* in_feat    = (const float*)d_in[2];
    const int*   row_indptr = (const int*)  d_in[3];
    const int*   col_idx    = (const int*)  d_in[4];
    float*       out        = (float*)      d_out;

    const int n  = in_sizes[3] - 1;   // N from indptr length
    const int n8 = in_sizes[2] / 8;   // uint4 count of fp16 copy

    // K1: convert (PDL primary)
    gat_convert_kernel<<<(n8 + 255) / 256, 256>>>((const float4*)in_feat, n8);

    // K2: fused GAT (PDL secondary)
    const int pairs  = (n + 1) / 2;
    const int blocks = (pairs + WPB - 1) / WPB;

    cudaLaunchConfig_t cfg = {};
    cfg.gridDim  = dim3(blocks, 1, 1);
    cfg.blockDim = dim3(WPB * 32, 1, 1);
    cfg.dynamicSmemBytes = 0;
    cfg.stream = 0;

    cudaLaunchAttribute attr;
    attr.id = cudaLaunchAttributeProgrammaticStreamSerialization;
    attr.val.programmaticStreamSerializationAllowed = 1;
    cfg.attrs = &attr;
    cfg.numAttrs = 1;

    cudaLaunchKernelEx(&cfg, fused_gat_pair_kernel,
                       attn_row, attn_col, row_indptr, col_idx, out, n);
}